// round 10
// baseline (speedup 1.0000x reference)
#include <cuda_runtime.h>
#include <cuda_fp16.h>

#define N_SRC 50000
#define N_DST 50000
#define D     128
#define K     8

// Scratch (no allocations allowed)
__device__ int    g_counters[N_SRC + N_DST]; // [0,N_SRC)=out_deg, rest=neg cnt
__device__ int    g_anyneg;                  // any category[i] == -1 ?
__device__ int    g_ptr[N_DST + 1];
__device__ int2   g_pairs[N_DST * K];        // (src, weight-bits); (0,0)=pad;
                                             // pair0.src = -1 => fallback path
__device__ __half g_hsrc[N_SRC * D];         // fp16 copy of h_src (12.8 MB)

// PDL plumbing
__device__ __forceinline__ void pdl_wait() {
    asm volatile("griddepcontrol.wait;" ::: "memory");
}
__device__ __forceinline__ void pdl_fire() {
    asm volatile("griddepcontrol.launch_dependents;" ::: "memory");
}

// Kernel 0: zero counters + category scan + h_src -> fp16 conversion.
// One thread per float4 of h_src (1.6M threads); low-id threads also zero.
__global__ void __launch_bounds__(256)
prologue_kernel(const float* __restrict__ h_src,
                const int* __restrict__ category, int n_src) {
    int i = blockIdx.x * blockDim.x + threadIdx.x;
    if (i < N_SRC + N_DST) g_counters[i] = 0;
    if (i == 0) g_anyneg = 0;
    if (i < n_src && __ldg(&category[i]) == -1)
        g_anyneg = 1;   // only value ever stored is 1: racy store is safe

    if (i < (N_SRC * D) / 4) {
        float4 v = __ldg(&((const float4*)h_src)[i]);
        __half2 h0 = __floats2half2_rn(v.x, v.y);
        __half2 h1 = __floats2half2_rn(v.z, v.w);
        ((uint2*)g_hsrc)[i] = make_uint2(*(unsigned*)&h0, *(unsigned*)&h1);
    }
    pdl_fire();
}

// Kernel 1: out-degree histogram + CSR ptr boundary scan. Category gather +
// neg atomics (escape-hatch feed) run ONLY if some category == -1.
__global__ void __launch_bounds__(256)
count_kernel(const int* __restrict__ src_idx,
             const int* __restrict__ dst_idx,
             const int* __restrict__ category, int E) {
    int e = blockIdx.x * blockDim.x + threadIdx.x;
    int s = 0, cur = 0;
    bool act = (e < E);
    if (act) {                       // pure inputs: prefetch before the wait
        s   = __ldg(&src_idx[e]);
        cur = __ldg(&dst_idx[e]);
    }
    int lane = threadIdx.x & 31;
    int prev = __shfl_up_sync(0xffffffffu, cur, 1);
    if (act && lane == 0) prev = (e == 0) ? -1 : __ldg(&dst_idx[e - 1]);

    pdl_wait();                      // counters zeroed beyond this point
    if (!act) return;

    atomicAdd(&g_counters[s], 1);
    if (g_anyneg) {                  // uniform branch; normally 0
        if (__ldg(&category[s]) == -1)
            atomicAdd(&g_counters[N_SRC + cur], 1);
    }
    for (int d = prev + 1; d <= cur; ++d) g_ptr[d] = e;
    if (e == E - 1)
        for (int d = cur + 1; d <= N_DST; ++d) g_ptr[d] = E;
    pdl_fire();
}

// Kernel 2: resolve sampling per (node,k), one thread each. Octet dedup via
// shuffles; both norms folded into the weight; (0,0) pads stay L1-resident
// in main. Escape-hatch nodes (neg>0 && deg>K) get a src=-1 sentinel.
__global__ void __launch_bounds__(256)
prep_kernel(const float* __restrict__ unif,
            const int* __restrict__ src_idx, int E) {
    int t = blockIdx.x * blockDim.x + threadIdx.x;
    bool act = (t < N_DST * K);
    int n = t >> 3;
    int k = t & 7;
    float u = 0.f;
    if (act) u = __ldg(&unif[t]);    // pure input: prefetch before the wait

    pdl_wait();                      // g_ptr / g_counters valid beyond here
    if (!act) return;

    int p0 = __ldg(&g_ptr[n]);
    int p1 = __ldg(&g_ptr[n + 1]);
    int deg = p1 - p0;
    bool small = (deg <= K);
    bool esc   = !small && (__ldg(&g_counters[N_SRC + n]) > 0);

    int src = 0;
    float w = 0.f;
    if (!small && !esc) {
        float fdeg = (float)deg;
        int off = min((int)floorf(u * fdeg), deg - 1);
        int eid = min(p0 + off, E - 1);
        src = __ldg(&src_idx[eid]);
        w = rsqrtf((float)max(__ldg(&g_counters[src]), 1)) * rsqrtf(fdeg);
    } else if (small && k < deg) {
        src = __ldg(&src_idx[p0 + k]);
        w = rsqrtf((float)max(__ldg(&g_counters[src]), 1)) *
            rsqrtf((float)max(deg, 1));
    }

    // Octet dedup — ALL lanes participate in the shuffles (no early return).
    int lane = threadIdx.x & 31;
    int base = lane & ~7;
    float wsum = 0.f;
    int first = k;
    #pragma unroll
    for (int j = 0; j < K; ++j) {
        int   sj = __shfl_sync(0xffffffffu, src, base + j);
        float wj = __shfl_sync(0xffffffffu, w,   base + j);
        if (sj == src) {
            wsum += wj;
            first = min(first, j);
        }
    }
    if (esc) {
        if (k == 0) g_pairs[t] = make_int2(-1, 0);
    } else {
        g_pairs[t] = (first == k) ? make_int2(src, __float_as_int(wsum))
                                  : make_int2(0, 0);
    }
    pdl_fire();
}

// Kernel 3: one warp per dst node, barrier-free. Gathers the fp16 copy:
// each lane reads 8 bytes (4 halfs) per sampled row -> 256 B/row total.
__global__ void __launch_bounds__(256)
main_kernel(const int* __restrict__ src_idx,
            float* __restrict__ out) {
    int warp = (blockIdx.x * blockDim.x + threadIdx.x) >> 5;  // grid exact
    int lane = threadIdx.x & 31;
    int n = warp;

    pdl_wait();                      // g_pairs + g_hsrc valid beyond here

    const int4* pb = (const int4*)(g_pairs + n * K);
    int4 q0 = __ldg(&pb[0]);
    int4 q1 = __ldg(&pb[1]);
    int4 q2 = __ldg(&pb[2]);
    int4 q3 = __ldg(&pb[3]);

    float4 acc = make_float4(0.f, 0.f, 0.f, 0.f);

    if (q0.x >= 0) {
        int   srcs[K] = {q0.x, q0.z, q1.x, q1.z, q2.x, q2.z, q3.x, q3.z};
        float ws[K]   = {__int_as_float(q0.y), __int_as_float(q0.w),
                         __int_as_float(q1.y), __int_as_float(q1.w),
                         __int_as_float(q2.y), __int_as_float(q2.w),
                         __int_as_float(q3.y), __int_as_float(q3.w)};
        #pragma unroll
        for (int k = 0; k < K; ++k) {
            const uint2* row = (const uint2*)(g_hsrc + (long long)srcs[k] * D);
            uint2 hv = __ldg(&row[lane]);
            float2 f0 = __half22float2(*(__half2*)&hv.x);
            float2 f1 = __half22float2(*(__half2*)&hv.y);
            float w = ws[k];
            acc.x += f0.x * w; acc.y += f0.y * w;
            acc.z += f1.x * w; acc.w += f1.y * w;
        }
        ((float4*)(out + (long long)n * D))[lane] = acc;
    } else {
        // Escape hatch (neg>0 && deg>K): full reduction over all edges.
        int p0 = __ldg(&g_ptr[n]);
        int p1 = __ldg(&g_ptr[n + 1]);
        int deg = p1 - p0;
        for (int e = p0; e < p1; ++e) {
            int s = __ldg(&src_idx[e]);
            float w = rsqrtf((float)max(__ldg(&g_counters[s]), 1));
            const uint2* row = (const uint2*)(g_hsrc + (long long)s * D);
            uint2 hv = __ldg(&row[lane]);
            float2 f0 = __half22float2(*(__half2*)&hv.x);
            float2 f1 = __half22float2(*(__half2*)&hv.y);
            acc.x += f0.x * w; acc.y += f0.y * w;
            acc.z += f1.x * w; acc.w += f1.y * w;
        }
        float innorm = rsqrtf((float)max(deg, 1));
        float4 o;
        o.x = acc.x * innorm; o.y = acc.y * innorm;
        o.z = acc.z * innorm; o.w = acc.w * innorm;
        ((float4*)(out + (long long)n * D))[lane] = o;
    }
}

// Helper: launch with the PDL programmatic-stream-serialization attribute.
template <typename... Args>
static void launch_pdl(void (*kern)(Args...), dim3 grid, dim3 block,
                       Args... args) {
    cudaLaunchAttribute attr[1];
    attr[0].id = cudaLaunchAttributeProgrammaticStreamSerialization;
    attr[0].val.programmaticStreamSerializationAllowed = 1;
    cudaLaunchConfig_t cfg{};
    cfg.gridDim = grid;
    cfg.blockDim = block;
    cfg.dynamicSmemBytes = 0;
    cfg.stream = 0;
    cfg.attrs = attr;
    cfg.numAttrs = 1;
    cudaLaunchKernelEx(&cfg, kern, args...);
}

extern "C" void kernel_launch(void* const* d_in, const int* in_sizes, int n_in,
                              void* d_out, int out_size) {
    const float* h_src    = (const float*)d_in[0];
    // d_in[1] = h_dst : unused by the reference computation
    const float* unif     = (const float*)d_in[2];
    const int*   src_idx  = (const int*)d_in[3];
    const int*   dst_idx  = (const int*)d_in[4];
    const int*   category = (const int*)d_in[5];
    float* out = (float*)d_out;

    int E = in_sizes[3];
    int n_src = in_sizes[5];

    int conv_threads = (N_SRC * D) / 4;        // 1.6M
    prologue_kernel<<<(conv_threads + 255) / 256, 256>>>(h_src, category, n_src);
    launch_pdl(count_kernel, dim3((E + 255) / 256), dim3(256),
               src_idx, dst_idx, category, E);
    launch_pdl(prep_kernel, dim3((N_DST * K + 255) / 256), dim3(256),
               unif, src_idx, E);
    launch_pdl(main_kernel, dim3((N_DST * 32) / 256), dim3(256),
               src_idx, out);
}

// round 11
// speedup vs baseline: 1.1535x; 1.1535x over previous
#include <cuda_runtime.h>
#include <cuda_fp16.h>

#define N_SRC 50000
#define N_DST 50000
#define D     128
#define K     8

// Scratch (no allocations allowed)
__device__ int    g_counters[N_SRC + N_DST]; // [0,N_SRC)=out_deg, rest=neg cnt
__device__ int    g_anyneg;                  // any category[i] == -1 ?
__device__ int    g_ptr[N_DST + 1];
__device__ int2   g_pairs[N_DST * K];        // (src, weight-bits); (0,0)=pad;
                                             // pair0.src = -1 => fallback path
__device__ __half g_hsrc[N_SRC * D];         // fp16 copy of h_src (12.8 MB)

// PDL plumbing
__device__ __forceinline__ void pdl_wait() {
    asm volatile("griddepcontrol.wait;" ::: "memory");
}
__device__ __forceinline__ void pdl_fire() {
    asm volatile("griddepcontrol.launch_dependents;" ::: "memory");
}

// Kernel 0: zero counters + category scan only (small, fast).
__global__ void __launch_bounds__(256)
zero_scan_kernel(const int* __restrict__ category, int n_src) {
    int i = blockIdx.x * blockDim.x + threadIdx.x;
    if (i < N_SRC + N_DST) g_counters[i] = 0;
    if (i == 0) g_anyneg = 0;
    if (i < n_src && __ldg(&category[i]) == -1)
        g_anyneg = 1;   // only value ever stored is 1: racy store is safe
    pdl_fire();
}

// Kernel 1: fp16 conversion (pre-wait: overlaps the prologue via PDL early
// launch; g_hsrc is only read by main, 2 kernels downstream) + out-degree
// histogram + CSR ptr boundary scan (post-wait).
__global__ void __launch_bounds__(256)
count_kernel(const float* __restrict__ h_src,
             const int* __restrict__ src_idx,
             const int* __restrict__ dst_idx,
             const int* __restrict__ category, int E) {
    int e = blockIdx.x * blockDim.x + threadIdx.x;
    int nthreads = (int)(gridDim.x * blockDim.x);

    // --- pre-wait work: h_src -> fp16 (independent of the prologue) ---------
    for (int i = e; i < (N_SRC * D) / 4; i += nthreads) {
        float4 v = __ldg(&((const float4*)h_src)[i]);
        __half2 h0 = __floats2half2_rn(v.x, v.y);
        __half2 h1 = __floats2half2_rn(v.z, v.w);
        ((uint2*)g_hsrc)[i] = make_uint2(*(unsigned*)&h0, *(unsigned*)&h1);
    }

    // pure inputs for the count phase: prefetch before the wait
    int s = 0, cur = 0;
    bool act = (e < E);
    if (act) {
        s   = __ldg(&src_idx[e]);
        cur = __ldg(&dst_idx[e]);
    }
    int lane = threadIdx.x & 31;
    int prev = __shfl_up_sync(0xffffffffu, cur, 1);
    if (act && lane == 0) prev = (e == 0) ? -1 : __ldg(&dst_idx[e - 1]);

    pdl_wait();                      // counters zeroed beyond this point
    if (act) {
        atomicAdd(&g_counters[s], 1);
        if (g_anyneg) {              // uniform branch; normally 0
            if (__ldg(&category[s]) == -1)
                atomicAdd(&g_counters[N_SRC + cur], 1);
        }
        for (int d = prev + 1; d <= cur; ++d) g_ptr[d] = e;
        if (e == E - 1)
            for (int d = cur + 1; d <= N_DST; ++d) g_ptr[d] = E;
    }
    pdl_fire();
}

// Kernel 2: resolve sampling per (node,k), one thread each. Octet dedup via
// shuffles; both norms folded into the weight; (0,0) pads stay L1-resident
// in main. Escape-hatch nodes (neg>0 && deg>K) get a src=-1 sentinel.
__global__ void __launch_bounds__(256)
prep_kernel(const float* __restrict__ unif,
            const int* __restrict__ src_idx, int E) {
    int t = blockIdx.x * blockDim.x + threadIdx.x;
    bool act = (t < N_DST * K);
    int n = t >> 3;
    int k = t & 7;
    float u = 0.f;
    if (act) u = __ldg(&unif[t]);    // pure input: prefetch before the wait

    pdl_wait();                      // g_ptr / g_counters valid beyond here
    if (!act) return;

    int p0 = __ldg(&g_ptr[n]);
    int p1 = __ldg(&g_ptr[n + 1]);
    int deg = p1 - p0;
    bool small = (deg <= K);
    bool esc   = !small && (__ldg(&g_counters[N_SRC + n]) > 0);

    int src = 0;
    float w = 0.f;
    if (!small && !esc) {
        float fdeg = (float)deg;
        int off = min((int)floorf(u * fdeg), deg - 1);
        int eid = min(p0 + off, E - 1);
        src = __ldg(&src_idx[eid]);
        w = rsqrtf((float)max(__ldg(&g_counters[src]), 1)) * rsqrtf(fdeg);
    } else if (small && k < deg) {
        src = __ldg(&src_idx[p0 + k]);
        w = rsqrtf((float)max(__ldg(&g_counters[src]), 1)) *
            rsqrtf((float)max(deg, 1));
    }

    // Octet dedup — ALL lanes participate in the shuffles (no early return).
    int lane = threadIdx.x & 31;
    int base = lane & ~7;
    float wsum = 0.f;
    int first = k;
    #pragma unroll
    for (int j = 0; j < K; ++j) {
        int   sj = __shfl_sync(0xffffffffu, src, base + j);
        float wj = __shfl_sync(0xffffffffu, w,   base + j);
        if (sj == src) {
            wsum += wj;
            first = min(first, j);
        }
    }
    if (esc) {
        if (k == 0) g_pairs[t] = make_int2(-1, 0);
    } else {
        g_pairs[t] = (first == k) ? make_int2(src, __float_as_int(wsum))
                                  : make_int2(0, 0);
    }
    pdl_fire();
}

// Kernel 3: one warp per dst node, barrier-free. Gathers the fp16 copy:
// each lane reads 8 bytes (4 halfs) per sampled row -> 256 B/row total.
__global__ void __launch_bounds__(256)
main_kernel(const int* __restrict__ src_idx,
            float* __restrict__ out) {
    int warp = (blockIdx.x * blockDim.x + threadIdx.x) >> 5;  // grid exact
    int lane = threadIdx.x & 31;
    int n = warp;

    pdl_wait();                      // g_pairs + g_hsrc valid beyond here

    const int4* pb = (const int4*)(g_pairs + n * K);
    int4 q0 = __ldg(&pb[0]);
    int4 q1 = __ldg(&pb[1]);
    int4 q2 = __ldg(&pb[2]);
    int4 q3 = __ldg(&pb[3]);

    float4 acc = make_float4(0.f, 0.f, 0.f, 0.f);

    if (q0.x >= 0) {
        int   srcs[K] = {q0.x, q0.z, q1.x, q1.z, q2.x, q2.z, q3.x, q3.z};
        float ws[K]   = {__int_as_float(q0.y), __int_as_float(q0.w),
                         __int_as_float(q1.y), __int_as_float(q1.w),
                         __int_as_float(q2.y), __int_as_float(q2.w),
                         __int_as_float(q3.y), __int_as_float(q3.w)};
        #pragma unroll
        for (int k = 0; k < K; ++k) {
            const uint2* row = (const uint2*)(g_hsrc + (long long)srcs[k] * D);
            uint2 hv = __ldg(&row[lane]);
            float2 f0 = __half22float2(*(__half2*)&hv.x);
            float2 f1 = __half22float2(*(__half2*)&hv.y);
            float w = ws[k];
            acc.x += f0.x * w; acc.y += f0.y * w;
            acc.z += f1.x * w; acc.w += f1.y * w;
        }
        ((float4*)(out + (long long)n * D))[lane] = acc;
    } else {
        // Escape hatch (neg>0 && deg>K): full reduction over all edges.
        int p0 = __ldg(&g_ptr[n]);
        int p1 = __ldg(&g_ptr[n + 1]);
        int deg = p1 - p0;
        for (int e = p0; e < p1; ++e) {
            int s = __ldg(&src_idx[e]);
            float w = rsqrtf((float)max(__ldg(&g_counters[s]), 1));
            const uint2* row = (const uint2*)(g_hsrc + (long long)s * D);
            uint2 hv = __ldg(&row[lane]);
            float2 f0 = __half22float2(*(__half2*)&hv.x);
            float2 f1 = __half22float2(*(__half2*)&hv.y);
            acc.x += f0.x * w; acc.y += f0.y * w;
            acc.z += f1.x * w; acc.w += f1.y * w;
        }
        float innorm = rsqrtf((float)max(deg, 1));
        float4 o;
        o.x = acc.x * innorm; o.y = acc.y * innorm;
        o.z = acc.z * innorm; o.w = acc.w * innorm;
        ((float4*)(out + (long long)n * D))[lane] = o;
    }
}

// Helper: launch with the PDL programmatic-stream-serialization attribute.
template <typename... Args>
static void launch_pdl(void (*kern)(Args...), dim3 grid, dim3 block,
                       Args... args) {
    cudaLaunchAttribute attr[1];
    attr[0].id = cudaLaunchAttributeProgrammaticStreamSerialization;
    attr[0].val.programmaticStreamSerializationAllowed = 1;
    cudaLaunchConfig_t cfg{};
    cfg.gridDim = grid;
    cfg.blockDim = block;
    cfg.dynamicSmemBytes = 0;
    cfg.stream = 0;
    cfg.attrs = attr;
    cfg.numAttrs = 1;
    cudaLaunchKernelEx(&cfg, kern, args...);
}

extern "C" void kernel_launch(void* const* d_in, const int* in_sizes, int n_in,
                              void* d_out, int out_size) {
    const float* h_src    = (const float*)d_in[0];
    // d_in[1] = h_dst : unused by the reference computation
    const float* unif     = (const float*)d_in[2];
    const int*   src_idx  = (const int*)d_in[3];
    const int*   dst_idx  = (const int*)d_in[4];
    const int*   category = (const int*)d_in[5];
    float* out = (float*)d_out;

    int E = in_sizes[3];
    int n_src = in_sizes[5];

    zero_scan_kernel<<<(N_SRC + N_DST + 255) / 256, 256>>>(category, n_src);
    launch_pdl(count_kernel, dim3((E + 255) / 256), dim3(256),
               h_src, src_idx, dst_idx, category, E);
    launch_pdl(prep_kernel, dim3((N_DST * K + 255) / 256), dim3(256),
               unif, src_idx, E);
    launch_pdl(main_kernel, dim3((N_DST * 32) / 256), dim3(256),
               src_idx, out);
}